// round 12
// baseline (speedup 1.0000x reference)
#include <cuda_runtime.h>
#include <cstdint>

// HybridQuanvolutionFraudNet — exact constant folding.
//
// log_softmax(logits, axis=-1) on [B,1] logits is bitwise 0.0f for every
// sample (x - x under JAX's max-subtraction), so the entire quanvolution +
// MLP pipeline is dead code. Exact output: 2048 float zeros. d_out is
// poisoned to 0xAA -> must be written.
//
// R11: R10 retry (fixed missing <cstdint>). Blackwell 256-bit global stores
// (st.global.v8.f32, sm_100+): 256 threads (8 warps — inside the measured
// sweet spot of >=4 warps / 1 store per thread), one STG.256 each; 8 KB in
// 8 warp-store instructions. Wall time expected neutral at the 4.608us
// per-launch floor (confirmed via CTA/warp/store-width/node-type sweeps).

__global__ __launch_bounds__(256, 1)
void hqfn_zero_vec8_kernel(float* __restrict__ out) {
    // 8 consecutive floats per thread, 32 B per lane, coalesced 1 KB per warp.
    float* p = out + threadIdx.x * 8;
    asm volatile(
        "st.global.v8.f32 [%0], {%1, %2, %3, %4, %5, %6, %7, %8};"
        :: "l"(p),
           "f"(0.f), "f"(0.f), "f"(0.f), "f"(0.f),
           "f"(0.f), "f"(0.f), "f"(0.f), "f"(0.f)
        : "memory");
}

// Generic fallback for arbitrary out_size (never taken for this problem's
// fixed 2048-element output; keeps kernel_launch shape-safe).
__global__ void hqfn_zero_scalar_kernel(float* __restrict__ out, int n) {
    int i = blockIdx.x * blockDim.x + threadIdx.x;
    if (i < n) out[i] = 0.0f;
}

extern "C" void kernel_launch(void* const* d_in, const int* in_sizes, int n_in,
                              void* d_out, int out_size) {
    (void)d_in; (void)in_sizes; (void)n_in;
    // 256-bit stores need 32 B alignment; cudaMalloc guarantees >=256 B.
    if (out_size == 2048 && (((uintptr_t)d_out) & 31u) == 0) {
        hqfn_zero_vec8_kernel<<<1, 256>>>((float*)d_out);
    } else {
        int threads = 256;
        int blocks = (out_size + threads - 1) / threads;
        hqfn_zero_scalar_kernel<<<blocks, threads>>>((float*)d_out, out_size);
    }
}

// round 13
// speedup vs baseline: 2.2817x; 2.2817x over previous
#include <cuda_runtime.h>

// HybridQuanvolutionFraudNet — exact constant folding. FINAL.
//
// The reference's last op is log_softmax(logits, axis=-1) on logits of shape
// [B, 1]. log_softmax over a singleton axis is identically 0.0f (x - x under
// JAX's max-subtraction) for every sample, independent of all inputs — so the
// entire 4-qubit quanvolution + 2-layer MLP pipeline is dead code. The exact
// output is 2048 float zeros (bitwise match, rel_err = 0.0). d_out is
// poisoned to 0xAA, so it must be written.
//
// Optimization history (full sweep; wall us / kernel us):
//   1 CTA x 512, STG.128 x1/thread : 4.608 / 3.10   <- best, reproduced 2x
//   1 CTA x 128, STG.128 x4/thread : 4.608 / 3.33
//   8 CTA x 256, scalar            : 5.216 / 3.81   (multi-CTA dispatch tail)
//   graph MEMSET node              : 5.344 / -      (heavier replay path)
//   1 CTA x  32, STG.128 x16/thread: 5.504 / 3.55   (serialized store drain)
//   1 CTA x 256, STG.256 x1/thread : 10.37 / 3.65   (wide-store retire cost)
// All pipes ~0%; duration is pure per-launch fixed cost. This is the floor.

__global__ __launch_bounds__(512, 1)
void hqfn_zero_vec4_kernel(float4* __restrict__ out) {
    out[threadIdx.x] = make_float4(0.f, 0.f, 0.f, 0.f);
}

// Generic fallback for arbitrary out_size (never taken for this problem's
// fixed 2048-element output; keeps kernel_launch shape-safe).
__global__ void hqfn_zero_scalar_kernel(float* __restrict__ out, int n) {
    int i = blockIdx.x * blockDim.x + threadIdx.x;
    if (i < n) out[i] = 0.0f;
}

extern "C" void kernel_launch(void* const* d_in, const int* in_sizes, int n_in,
                              void* d_out, int out_size) {
    (void)d_in; (void)in_sizes; (void)n_in;
    if (out_size == 2048) {
        // 512 threads x float4 = 2048 floats; one block, one STG.128 each.
        hqfn_zero_vec4_kernel<<<1, 512>>>((float4*)d_out);
    } else {
        int threads = 256;
        int blocks = (out_size + threads - 1) / threads;
        hqfn_zero_scalar_kernel<<<blocks, threads>>>((float*)d_out, out_size);
    }
}